// round 1
// baseline (speedup 1.0000x reference)
#include <cuda_runtime.h>
#include <math.h>

#define N_TOK 384
#define TDIM 768
#define VDIM 768
#define CDIM 1536
#define FF_DIM 2048
#define NH 4
#define NLAYERS 2

#define BM 64
#define BN 64
#define BK 16

// ---------------- scratch (no allocations allowed) ----------------
// offsets in floats
#define OFF_X   0LL
#define OFF_X2  589824LL
#define OFF_QKV 1179648LL
#define OFF_SC  2949120LL
#define OFF_O   3538944LL
#define OFF_Y   4128768LL
#define OFF_H   4718592LL
#define OFF_A   5505024LL
#define OFF_C   5505792LL
#define OFF_RC  5506560LL
#define OFF_RL  5506944LL
#define OFF_CL  5507328LL
#define BUF_TOTAL 5507712LL

__device__ float g_buf[BUF_TOTAL];

// ---------------- elementwise helpers ----------------
__global__ void copy_k(float* __restrict__ dst, const float* __restrict__ src, int n) {
    int i = blockIdx.x * blockDim.x + threadIdx.x;
    if (i < n) dst[i] = src[i];
}

__global__ void concat_k(float* __restrict__ dst, const float* __restrict__ te,
                         const float* __restrict__ vis) {
    int i = blockIdx.x * blockDim.x + threadIdx.x;
    if (i < N_TOK * CDIM) {
        int r = i / CDIM, c = i % CDIM;
        dst[i] = (c < TDIM) ? te[r * TDIM + c] : vis[r * VDIM + (c - TDIM)];
    }
}

// ---------------- GEMM: C = alpha * A(MxK) @ W(NcxK)^T + bias ----------------
__global__ void __launch_bounds__(256) gemm_nt_kernel(
    const float* __restrict__ A, int lda, long long aZ,
    const float* __restrict__ W, int ldw, long long wZ,
    const float* __restrict__ Bias,
    float* __restrict__ C, int ldc, long long cZ,
    int K, float alpha, int relu)
{
    A += blockIdx.z * aZ; W += blockIdx.z * wZ; C += blockIdx.z * cZ;
    __shared__ float As[BM][BK + 1];
    __shared__ float Bs[BN][BK + 1];
    int tid = threadIdx.x;
    int tx = tid & 15, ty = tid >> 4;
    int m0 = blockIdx.y * BM, n0 = blockIdx.x * BN;
    int lrow = tid >> 2, lc = (tid & 3) * 4;
    const float* Ap = A + (long long)(m0 + lrow) * lda + lc;
    const float* Wp = W + (long long)(n0 + lrow) * ldw + lc;
    float acc[4][4] = {};
    for (int k0 = 0; k0 < K; k0 += BK) {
        float4 av = *(const float4*)(Ap + k0);
        float4 wv = *(const float4*)(Wp + k0);
        As[lrow][lc + 0] = av.x; As[lrow][lc + 1] = av.y;
        As[lrow][lc + 2] = av.z; As[lrow][lc + 3] = av.w;
        Bs[lrow][lc + 0] = wv.x; Bs[lrow][lc + 1] = wv.y;
        Bs[lrow][lc + 2] = wv.z; Bs[lrow][lc + 3] = wv.w;
        __syncthreads();
#pragma unroll
        for (int k = 0; k < BK; k++) {
            float a0 = As[ty * 4 + 0][k], a1 = As[ty * 4 + 1][k];
            float a2 = As[ty * 4 + 2][k], a3 = As[ty * 4 + 3][k];
            float b0 = Bs[tx * 4 + 0][k], b1 = Bs[tx * 4 + 1][k];
            float b2 = Bs[tx * 4 + 2][k], b3 = Bs[tx * 4 + 3][k];
            acc[0][0] += a0 * b0; acc[0][1] += a0 * b1; acc[0][2] += a0 * b2; acc[0][3] += a0 * b3;
            acc[1][0] += a1 * b0; acc[1][1] += a1 * b1; acc[1][2] += a1 * b2; acc[1][3] += a1 * b3;
            acc[2][0] += a2 * b0; acc[2][1] += a2 * b1; acc[2][2] += a2 * b2; acc[2][3] += a2 * b3;
            acc[3][0] += a3 * b0; acc[3][1] += a3 * b1; acc[3][2] += a3 * b2; acc[3][3] += a3 * b3;
        }
        __syncthreads();
    }
#pragma unroll
    for (int i = 0; i < 4; i++) {
        float* Cr = C + (long long)(m0 + ty * 4 + i) * ldc + n0 + tx * 4;
#pragma unroll
        for (int j = 0; j < 4; j++) {
            float v = acc[i][j] * alpha;
            if (Bias) v += Bias[n0 + tx * 4 + j];
            if (relu) v = fmaxf(v, 0.f);
            Cr[j] = v;
        }
    }
}

// ---------------- GEMM: C = A(MxK) @ B(KxNc) ----------------
__global__ void __launch_bounds__(256) gemm_nn_kernel(
    const float* __restrict__ A, int lda, long long aZ,
    const float* __restrict__ B, int ldb, long long bZ,
    float* __restrict__ C, int ldc, long long cZ,
    int K)
{
    A += blockIdx.z * aZ; B += blockIdx.z * bZ; C += blockIdx.z * cZ;
    __shared__ float As[BM][BK + 1];
    __shared__ float Bs[BK][BN + 4];
    int tid = threadIdx.x;
    int tx = tid & 15, ty = tid >> 4;
    int m0 = blockIdx.y * BM, n0 = blockIdx.x * BN;
    int lrow = tid >> 2, lc = (tid & 3) * 4;
    int kk = tid >> 4, ns = (tid & 15) * 4;
    const float* Ap = A + (long long)(m0 + lrow) * lda + lc;
    const float* Bp = B + (long long)kk * ldb + n0 + ns;
    float acc[4][4] = {};
    for (int k0 = 0; k0 < K; k0 += BK) {
        float4 av = *(const float4*)(Ap + k0);
        float4 bv = *(const float4*)(Bp + (long long)k0 * ldb);
        As[lrow][lc + 0] = av.x; As[lrow][lc + 1] = av.y;
        As[lrow][lc + 2] = av.z; As[lrow][lc + 3] = av.w;
        Bs[kk][ns + 0] = bv.x; Bs[kk][ns + 1] = bv.y;
        Bs[kk][ns + 2] = bv.z; Bs[kk][ns + 3] = bv.w;
        __syncthreads();
#pragma unroll
        for (int k = 0; k < BK; k++) {
            float a0 = As[ty * 4 + 0][k], a1 = As[ty * 4 + 1][k];
            float a2 = As[ty * 4 + 2][k], a3 = As[ty * 4 + 3][k];
            float b0 = Bs[k][tx * 4 + 0], b1 = Bs[k][tx * 4 + 1];
            float b2 = Bs[k][tx * 4 + 2], b3 = Bs[k][tx * 4 + 3];
            acc[0][0] += a0 * b0; acc[0][1] += a0 * b1; acc[0][2] += a0 * b2; acc[0][3] += a0 * b3;
            acc[1][0] += a1 * b0; acc[1][1] += a1 * b1; acc[1][2] += a1 * b2; acc[1][3] += a1 * b3;
            acc[2][0] += a2 * b0; acc[2][1] += a2 * b1; acc[2][2] += a2 * b2; acc[2][3] += a2 * b3;
            acc[3][0] += a3 * b0; acc[3][1] += a3 * b1; acc[3][2] += a3 * b2; acc[3][3] += a3 * b3;
        }
        __syncthreads();
    }
#pragma unroll
    for (int i = 0; i < 4; i++) {
        float* Cr = C + (long long)(m0 + ty * 4 + i) * ldc + n0 + tx * 4;
#pragma unroll
        for (int j = 0; j < 4; j++) Cr[j] = acc[i][j];
    }
}

// ---------------- row softmax ----------------
__global__ void softmax_rows(float* __restrict__ S, int n) {
    float* row = S + (long long)blockIdx.x * n;
    __shared__ float red[128];
    int tid = threadIdx.x;
    float m = -1e30f;
    for (int j = tid; j < n; j += 128) m = fmaxf(m, row[j]);
    red[tid] = m; __syncthreads();
    for (int off = 64; off; off >>= 1) {
        if (tid < off) red[tid] = fmaxf(red[tid], red[tid + off]);
        __syncthreads();
    }
    m = red[0]; __syncthreads();
    float s = 0.f;
    for (int j = tid; j < n; j += 128) { float e = expf(row[j] - m); row[j] = e; s += e; }
    red[tid] = s; __syncthreads();
    for (int off = 64; off; off >>= 1) {
        if (tid < off) red[tid] += red[tid + off];
        __syncthreads();
    }
    float inv = 1.0f / red[0];
    for (int j = tid; j < n; j += 128) row[j] *= inv;
}

// ---------------- x = LN(x + delta) ----------------
__global__ void ln_res_kernel(float* __restrict__ x, const float* __restrict__ delta,
                              const float* __restrict__ s, const float* __restrict__ b, int d) {
    float* xr = x + (long long)blockIdx.x * d;
    const float* dr = delta + (long long)blockIdx.x * d;
    __shared__ float red[256];
    int tid = threadIdx.x;
    float sum = 0.f;
    for (int j = tid; j < d; j += 256) { float v = xr[j] + dr[j]; xr[j] = v; sum += v; }
    red[tid] = sum; __syncthreads();
    for (int off = 128; off; off >>= 1) {
        if (tid < off) red[tid] += red[tid + off];
        __syncthreads();
    }
    float mean = red[0] / d; __syncthreads();
    float s2 = 0.f;
    for (int j = tid; j < d; j += 256) { float v = xr[j] - mean; s2 += v * v; }
    red[tid] = s2; __syncthreads();
    for (int off = 128; off; off >>= 1) {
        if (tid < off) red[tid] += red[tid + off];
        __syncthreads();
    }
    float inv = rsqrtf(red[0] / d + 1e-5f);
    __syncthreads();
    for (int j = tid; j < d; j += 256) xr[j] = (xr[j] - mean) * inv * s[j] + b[j];
}

// ---------------- final linear: a = x@w[:, :CD]^T + b ; c = x@w[:, CD:]^T ----------------
__global__ void lin_kernel(const float* __restrict__ x, const float* __restrict__ w,
                           const float* __restrict__ b, float* __restrict__ a,
                           float* __restrict__ c) {
    int i = blockIdx.x;
    const float* xr = x + (long long)i * CDIM;
    __shared__ float red[4][256];
    int tid = threadIdx.x;
    float s0 = 0, s1 = 0, s2 = 0, s3 = 0;
    for (int k = tid; k < CDIM; k += 256) {
        float xv = xr[k];
        s0 += xv * w[k];
        s1 += xv * w[2 * CDIM + k];
        s2 += xv * w[CDIM + k];
        s3 += xv * w[2 * CDIM + CDIM + k];
    }
    red[0][tid] = s0; red[1][tid] = s1; red[2][tid] = s2; red[3][tid] = s3;
    __syncthreads();
    for (int off = 128; off; off >>= 1) {
        if (tid < off) {
            red[0][tid] += red[0][tid + off];
            red[1][tid] += red[1][tid + off];
            red[2][tid] += red[2][tid + off];
            red[3][tid] += red[3][tid + off];
        }
        __syncthreads();
    }
    if (tid == 0) {
        a[2 * i]     = red[0][0] + b[0];
        a[2 * i + 1] = red[1][0] + b[1];
        c[2 * i]     = red[2][0];
        c[2 * i + 1] = red[3][0];
    }
}

// ---------------- pairwise probs + per-row loss partials ----------------
__global__ void pair_kernel(const float* __restrict__ a, const float* __restrict__ c,
                            const int* __restrict__ gt, float* __restrict__ probs,
                            float* __restrict__ rowcell, float* __restrict__ rowlink) {
    int i = blockIdx.x, j = threadIdx.x;  // 384 threads
    float l0 = a[2 * i] + c[2 * j];
    float l1 = a[2 * i + 1] + c[2 * j + 1];
    float m = fmaxf(l0, l1);
    float e0 = expf(l0 - m), e1 = expf(l1 - m);
    float inv = 1.0f / (e0 + e1);
    float p0 = e0 * inv, p1 = e1 * inv;
    long long idx = ((long long)i * N_TOK + j) * 2;
    probs[idx] = p0; probs[idx + 1] = p1;
    // log_softmax applied to (p0, p1)
    float mm = fmaxf(p0, p1);
    float lse = mm + logf(expf(p0 - mm) + expf(p1 - mm));
    float pg = gt[i * N_TOK + j] ? p1 : p0;
    float cell = lse - pg;  // == -(pg - lse)

    __shared__ float red[512];
    red[j] = cell;
    if (j < 128) red[384 + j] = 0.f;
    __syncthreads();
    for (int off = 256; off; off >>= 1) {
        if (j < off) red[j] += red[j + off];
        __syncthreads();
    }
    if (j == 0) rowcell[i] = red[0];
    __syncthreads();
    red[j] = p1;
    if (j < 128) red[384 + j] = 0.f;
    __syncthreads();
    for (int off = 256; off; off >>= 1) {
        if (j < off) red[j] += red[j + off];
        __syncthreads();
    }
    if (j == 0) rowlink[i] = red[0];
}

__global__ void col_kernel(const float* __restrict__ probs, float* __restrict__ collink) {
    int j = blockIdx.x; int tid = threadIdx.x;  // 128
    float s = 0.f;
    for (int i = tid; i < N_TOK; i += 128) s += probs[((long long)i * N_TOK + j) * 2 + 1];
    __shared__ float red[128];
    red[tid] = s; __syncthreads();
    for (int off = 64; off; off >>= 1) {
        if (tid < off) red[tid] += red[tid + off];
        __syncthreads();
    }
    if (tid == 0) collink[j] = red[0];
}

__global__ void final_kernel(const float* __restrict__ rowcell, const float* __restrict__ rowlink,
                             const float* __restrict__ collink, float* __restrict__ out,
                             int out_size) {
    __shared__ float r1[512], r2[512];
    int tid = threadIdx.x;  // 512
    r1[tid] = (tid < N_TOK) ? rowcell[tid] : 0.f;
    r2[tid] = (tid < N_TOK - 1) ? fabsf(rowlink[tid] + collink[tid] - 1.0f) : 0.f;
    __syncthreads();
    for (int off = 256; off; off >>= 1) {
        if (tid < off) { r1[tid] += r1[tid + off]; r2[tid] += r2[tid + off]; }
        __syncthreads();
    }
    if (tid == 0 && out_size >= N_TOK * N_TOK * 2 + 2) {
        out[N_TOK * N_TOK * 2]     = r1[0] / (float)N_TOK;
        out[N_TOK * N_TOK * 2 + 1] = r2[0];
    }
}

// ---------------- host orchestration ----------------
struct EncWeights {
    const float *qkv_w, *qkv_b, *out_w, *out_b, *ln1_s, *ln1_b;
    const float *ff1_w, *ff1_b, *ff2_w, *ff2_b, *ln2_s, *ln2_b;
};

static void run_encoder(float* x, int d, const EncWeights& w,
                        float* qkv, float* sc, float* o, float* y, float* h) {
    const int M = N_TOK;
    const int hd = d / NH;
    const float scale = 1.0f / sqrtf((float)hd);
    for (int l = 0; l < NLAYERS; l++) {
        const float* Wq = w.qkv_w + (long long)l * 3 * d * d;
        const float* Bq = w.qkv_b + (long long)l * 3 * d;
        // qkv = x @ Wq^T + Bq
        gemm_nt_kernel<<<dim3(3 * d / BN, M / BM, 1), 256>>>(
            x, d, 0, Wq, d, 0, Bq, qkv, 3 * d, 0, d, 1.f, 0);
        // scores[h] = Q_h @ K_h^T * scale   (batched over heads)
        gemm_nt_kernel<<<dim3(M / BN, M / BM, NH), 256>>>(
            qkv, 3 * d, hd, qkv + d, 3 * d, hd, nullptr,
            sc, M, (long long)M * M, hd, scale, 0);
        softmax_rows<<<NH * M, 128>>>(sc, M);
        // o[:, h*hd:] = attn_h @ V_h  (batched)
        gemm_nn_kernel<<<dim3(hd / BN, M / BM, NH), 256>>>(
            sc, M, (long long)M * M, qkv + 2 * d, 3 * d, hd,
            o, d, hd, M);
        // y = o @ out_w^T + out_b
        gemm_nt_kernel<<<dim3(d / BN, M / BM, 1), 256>>>(
            o, d, 0, w.out_w + (long long)l * d * d, d, 0, w.out_b + (long long)l * d,
            y, d, 0, d, 1.f, 0);
        ln_res_kernel<<<M, 256>>>(x, y, w.ln1_s + (long long)l * d, w.ln1_b + (long long)l * d, d);
        // h = relu(x @ ff1^T + b1)
        gemm_nt_kernel<<<dim3(FF_DIM / BN, M / BM, 1), 256>>>(
            x, d, 0, w.ff1_w + (long long)l * FF_DIM * d, d, 0, w.ff1_b + (long long)l * FF_DIM,
            h, FF_DIM, 0, d, 1.f, 1);
        // y = h @ ff2^T + b2
        gemm_nt_kernel<<<dim3(d / BN, M / BM, 1), 256>>>(
            h, FF_DIM, 0, w.ff2_w + (long long)l * d * FF_DIM, FF_DIM, 0, w.ff2_b + (long long)l * d,
            y, d, 0, FF_DIM, 1.f, 0);
        ln_res_kernel<<<M, 256>>>(x, y, w.ln2_s + (long long)l * d, w.ln2_b + (long long)l * d, d);
    }
}

extern "C" void kernel_launch(void* const* d_in, const int* in_sizes, int n_in,
                              void* d_out, int out_size) {
    const float* text   = (const float*)d_in[0];
    const float* vision = (const float*)d_in[1];
    const int*   gt     = (const int*)d_in[2];

    EncWeights tw = {
        (const float*)d_in[3],  (const float*)d_in[4],  (const float*)d_in[5],
        (const float*)d_in[6],  (const float*)d_in[7],  (const float*)d_in[8],
        (const float*)d_in[9],  (const float*)d_in[10], (const float*)d_in[11],
        (const float*)d_in[12], (const float*)d_in[13], (const float*)d_in[14]
    };
    EncWeights cw = {
        (const float*)d_in[15], (const float*)d_in[16], (const float*)d_in[17],
        (const float*)d_in[18], (const float*)d_in[19], (const float*)d_in[20],
        (const float*)d_in[21], (const float*)d_in[22], (const float*)d_in[23],
        (const float*)d_in[24], (const float*)d_in[25], (const float*)d_in[26]
    };
    const float* lin_w = (const float*)d_in[27];
    const float* lin_b = (const float*)d_in[28];

    float* buf = nullptr;
    cudaGetSymbolAddress((void**)&buf, g_buf);
    float* x    = buf + OFF_X;
    float* x2   = buf + OFF_X2;
    float* qkv  = buf + OFF_QKV;
    float* sc   = buf + OFF_SC;
    float* o    = buf + OFF_O;
    float* y    = buf + OFF_Y;
    float* h    = buf + OFF_H;
    float* ga   = buf + OFF_A;
    float* gc   = buf + OFF_C;
    float* rcel = buf + OFF_RC;
    float* rlnk = buf + OFF_RL;
    float* clnk = buf + OFF_CL;

    // text encoder
    copy_k<<<(N_TOK * TDIM + 255) / 256, 256>>>(x, text, N_TOK * TDIM);
    run_encoder(x, TDIM, tw, qkv, sc, o, y, h);

    // concat + cross encoder
    concat_k<<<(N_TOK * CDIM + 255) / 256, 256>>>(x2, x, vision);
    run_encoder(x2, CDIM, cw, qkv, sc, o, y, h);

    // final linear
    lin_kernel<<<N_TOK, 256>>>(x2, lin_w, lin_b, ga, gc);

    // pairwise probs + losses
    float* out = (float*)d_out;
    pair_kernel<<<N_TOK, N_TOK>>>(ga, gc, gt, out, rcel, rlnk);
    col_kernel<<<N_TOK, 128>>>(out, clnk);
    final_kernel<<<1, 512>>>(rcel, rlnk, clnk, out, out_size);
}

// round 2
// speedup vs baseline: 1.5619x; 1.5619x over previous
#include <cuda_runtime.h>
#include <math.h>

#define N_TOK 384
#define TDIM 768
#define VDIM 768
#define CDIM 1536
#define FF_DIM 2048
#define NH 4
#define NLAYERS 2

// ---------------- scratch (no allocations allowed) ----------------
#define OFF_X   0LL
#define OFF_X2  589824LL
#define OFF_QKV 1179648LL
#define OFF_SC  2949120LL
#define OFF_O   3538944LL
#define OFF_Y   4128768LL
#define OFF_H   4718592LL
#define OFF_A   5505024LL
#define OFF_C   5505792LL
#define OFF_RC  5506560LL
#define OFF_RL  5506944LL
#define OFF_CL  5507328LL
#define BUF_TOTAL 5507712LL

__device__ float g_buf[BUF_TOTAL];

// ---------------- helpers ----------------
__device__ __forceinline__ unsigned f2tf(float x) {
    unsigned u;
    asm("cvt.rna.tf32.f32 %0, %1;" : "=r"(u) : "f"(x));
    return u;
}

__device__ __forceinline__ void mma8(float* c, const unsigned* a, const unsigned* b) {
    asm volatile(
        "mma.sync.aligned.m16n8k8.row.col.f32.tf32.tf32.f32 "
        "{%0,%1,%2,%3},{%4,%5,%6,%7},{%8,%9},{%0,%1,%2,%3};"
        : "+f"(c[0]), "+f"(c[1]), "+f"(c[2]), "+f"(c[3])
        : "r"(a[0]), "r"(a[1]), "r"(a[2]), "r"(a[3]), "r"(b[0]), "r"(b[1]));
}

__global__ void copy_k(float* __restrict__ dst, const float* __restrict__ src, int n) {
    int i = blockIdx.x * blockDim.x + threadIdx.x;
    if (i < n) dst[i] = src[i];
}

__global__ void concat_k(float* __restrict__ dst, const float* __restrict__ te,
                         const float* __restrict__ vis) {
    int i = blockIdx.x * blockDim.x + threadIdx.x;
    if (i < N_TOK * CDIM) {
        int r = i / CDIM, c = i % CDIM;
        dst[i] = (c < TDIM) ? te[r * TDIM + c] : vis[r * VDIM + (c - TDIM)];
    }
}

// ---------------- tf32 tensor-core GEMM tiles ----------------
// Block tile 64x64, BK=16, 128 threads (4 warps in 2x2, each warp 32x32).
#define SPAD 20   // smem row stride in words; conflict-free fragment reads

// NT: C = alpha * A(MxK,row) @ W(NxK,row)^T + bias, optional relu. Batched via z.
__global__ void __launch_bounds__(128) tf32_nt(
    const float* __restrict__ A, int lda, long long aZ,
    const float* __restrict__ W, int ldw, long long wZ,
    const float* __restrict__ Bias,
    float* __restrict__ C, int ldc, long long cZ,
    int K, float alpha, int relu)
{
    A += blockIdx.z * aZ; W += blockIdx.z * wZ; C += blockIdx.z * cZ;
    __shared__ unsigned As[2][64 * SPAD];
    __shared__ unsigned Bs[2][64 * SPAD];
    int tid = threadIdx.x;
    int warp = tid >> 5, lane = tid & 31;
    int g = lane >> 2, tg = lane & 3;
    int wm = (warp >> 1) * 32, wn = (warp & 1) * 32;
    int m0 = blockIdx.y * 64, n0 = blockIdx.x * 64;

    int lrow = tid >> 1;          // 0..63
    int lcol = (tid & 1) * 8;     // 0 or 8
    const float* Ap = A + (long long)(m0 + lrow) * lda + lcol;
    const float* Wp = W + (long long)(n0 + lrow) * ldw + lcol;
    int sidx = lrow * SPAD + lcol;

    float acc[2][4][4] = {};

    int ntile = K / 16;
    // preload tile 0
    {
        float4 a0 = *(const float4*)(Ap);
        float4 a1 = *(const float4*)(Ap + 4);
        float4 w0 = *(const float4*)(Wp);
        float4 w1 = *(const float4*)(Wp + 4);
        *(uint4*)&As[0][sidx]     = make_uint4(f2tf(a0.x), f2tf(a0.y), f2tf(a0.z), f2tf(a0.w));
        *(uint4*)&As[0][sidx + 4] = make_uint4(f2tf(a1.x), f2tf(a1.y), f2tf(a1.z), f2tf(a1.w));
        *(uint4*)&Bs[0][sidx]     = make_uint4(f2tf(w0.x), f2tf(w0.y), f2tf(w0.z), f2tf(w0.w));
        *(uint4*)&Bs[0][sidx + 4] = make_uint4(f2tf(w1.x), f2tf(w1.y), f2tf(w1.z), f2tf(w1.w));
    }
    __syncthreads();
    int p = 0;
    for (int it = 0; it < ntile; it++) {
        float4 na0, na1, nw0, nw1;
        if (it + 1 < ntile) {
            int ko = (it + 1) * 16;
            na0 = *(const float4*)(Ap + ko);
            na1 = *(const float4*)(Ap + ko + 4);
            nw0 = *(const float4*)(Wp + ko);
            nw1 = *(const float4*)(Wp + ko + 4);
        }
#pragma unroll
        for (int ks = 0; ks < 2; ks++) {
            int kb = ks * 8;
            unsigned a[2][4], b[4][2];
#pragma unroll
            for (int mt = 0; mt < 2; mt++) {
                const unsigned* base = &As[p][(wm + mt * 16 + g) * SPAD + kb + tg];
                a[mt][0] = base[0];
                a[mt][1] = base[8 * SPAD];
                a[mt][2] = base[4];
                a[mt][3] = base[8 * SPAD + 4];
            }
#pragma unroll
            for (int nt = 0; nt < 4; nt++) {
                const unsigned* base = &Bs[p][(wn + nt * 8 + g) * SPAD + kb + tg];
                b[nt][0] = base[0];
                b[nt][1] = base[4];
            }
#pragma unroll
            for (int mt = 0; mt < 2; mt++)
#pragma unroll
                for (int nt = 0; nt < 4; nt++)
                    mma8(acc[mt][nt], a[mt], b[nt]);
        }
        if (it + 1 < ntile) {
            int q = p ^ 1;
            *(uint4*)&As[q][sidx]     = make_uint4(f2tf(na0.x), f2tf(na0.y), f2tf(na0.z), f2tf(na0.w));
            *(uint4*)&As[q][sidx + 4] = make_uint4(f2tf(na1.x), f2tf(na1.y), f2tf(na1.z), f2tf(na1.w));
            *(uint4*)&Bs[q][sidx]     = make_uint4(f2tf(nw0.x), f2tf(nw0.y), f2tf(nw0.z), f2tf(nw0.w));
            *(uint4*)&Bs[q][sidx + 4] = make_uint4(f2tf(nw1.x), f2tf(nw1.y), f2tf(nw1.z), f2tf(nw1.w));
        }
        __syncthreads();
        p ^= 1;
    }

#pragma unroll
    for (int mt = 0; mt < 2; mt++) {
#pragma unroll
        for (int nt = 0; nt < 4; nt++) {
            int col = n0 + wn + nt * 8 + 2 * tg;
            float b0 = 0.f, b1 = 0.f;
            if (Bias) { b0 = Bias[col]; b1 = Bias[col + 1]; }
            int row = m0 + wm + mt * 16 + g;
            float2 v0, v1;
            v0.x = acc[mt][nt][0] * alpha + b0;
            v0.y = acc[mt][nt][1] * alpha + b1;
            v1.x = acc[mt][nt][2] * alpha + b0;
            v1.y = acc[mt][nt][3] * alpha + b1;
            if (relu) {
                v0.x = fmaxf(v0.x, 0.f); v0.y = fmaxf(v0.y, 0.f);
                v1.x = fmaxf(v1.x, 0.f); v1.y = fmaxf(v1.y, 0.f);
            }
            *(float2*)&C[(long long)row * ldc + col] = v0;
            *(float2*)&C[(long long)(row + 8) * ldc + col] = v1;
        }
    }
}

// NN: C = A(MxK,row) @ B(KxN,row). Batched via z. (B transposed into smem.)
__global__ void __launch_bounds__(128) tf32_nn(
    const float* __restrict__ A, int lda, long long aZ,
    const float* __restrict__ B, int ldb, long long bZ,
    float* __restrict__ C, int ldc, long long cZ,
    int K)
{
    A += blockIdx.z * aZ; B += blockIdx.z * bZ; C += blockIdx.z * cZ;
    __shared__ unsigned As[2][64 * SPAD];
    __shared__ unsigned Bs[2][64 * SPAD];
    int tid = threadIdx.x;
    int warp = tid >> 5, lane = tid & 31;
    int g = lane >> 2, tg = lane & 3;
    int wm = (warp >> 1) * 32, wn = (warp & 1) * 32;
    int m0 = blockIdx.y * 64, n0 = blockIdx.x * 64;

    int lrow = tid >> 1;
    int lcol = (tid & 1) * 8;
    const float* Ap = A + (long long)(m0 + lrow) * lda + lcol;
    int sidx = lrow * SPAD + lcol;

    // B loads: 16 rows x 64 cols per tile = 256 float4; thread handles 2.
    int f0 = tid * 2;
    int bk0 = f0 >> 4, bc0 = (f0 & 15) * 4;   // row k, col within tile
    int bk1 = (f0 + 1) >> 4, bc1 = ((f0 + 1) & 15) * 4;
    const float* Bp0 = B + (long long)bk0 * ldb + n0 + bc0;
    const float* Bp1 = B + (long long)bk1 * ldb + n0 + bc1;

    float acc[2][4][4] = {};
    int ntile = K / 16;
    {
        float4 a0 = *(const float4*)(Ap);
        float4 a1 = *(const float4*)(Ap + 4);
        float4 v0 = *(const float4*)(Bp0);
        float4 v1 = *(const float4*)(Bp1);
        *(uint4*)&As[0][sidx]     = make_uint4(f2tf(a0.x), f2tf(a0.y), f2tf(a0.z), f2tf(a0.w));
        *(uint4*)&As[0][sidx + 4] = make_uint4(f2tf(a1.x), f2tf(a1.y), f2tf(a1.z), f2tf(a1.w));
        Bs[0][(bc0 + 0) * SPAD + bk0] = f2tf(v0.x);
        Bs[0][(bc0 + 1) * SPAD + bk0] = f2tf(v0.y);
        Bs[0][(bc0 + 2) * SPAD + bk0] = f2tf(v0.z);
        Bs[0][(bc0 + 3) * SPAD + bk0] = f2tf(v0.w);
        Bs[0][(bc1 + 0) * SPAD + bk1] = f2tf(v1.x);
        Bs[0][(bc1 + 1) * SPAD + bk1] = f2tf(v1.y);
        Bs[0][(bc1 + 2) * SPAD + bk1] = f2tf(v1.z);
        Bs[0][(bc1 + 3) * SPAD + bk1] = f2tf(v1.w);
    }
    __syncthreads();
    int p = 0;
    for (int it = 0; it < ntile; it++) {
        float4 na0, na1, nv0, nv1;
        if (it + 1 < ntile) {
            int ko = (it + 1) * 16;
            na0 = *(const float4*)(Ap + ko);
            na1 = *(const float4*)(Ap + ko + 4);
            nv0 = *(const float4*)(Bp0 + (long long)ko * ldb);
            nv1 = *(const float4*)(Bp1 + (long long)ko * ldb);
        }
#pragma unroll
        for (int ks = 0; ks < 2; ks++) {
            int kb = ks * 8;
            unsigned a[2][4], b[4][2];
#pragma unroll
            for (int mt = 0; mt < 2; mt++) {
                const unsigned* base = &As[p][(wm + mt * 16 + g) * SPAD + kb + tg];
                a[mt][0] = base[0];
                a[mt][1] = base[8 * SPAD];
                a[mt][2] = base[4];
                a[mt][3] = base[8 * SPAD + 4];
            }
#pragma unroll
            for (int nt = 0; nt < 4; nt++) {
                const unsigned* base = &Bs[p][(wn + nt * 8 + g) * SPAD + kb + tg];
                b[nt][0] = base[0];
                b[nt][1] = base[4];
            }
#pragma unroll
            for (int mt = 0; mt < 2; mt++)
#pragma unroll
                for (int nt = 0; nt < 4; nt++)
                    mma8(acc[mt][nt], a[mt], b[nt]);
        }
        if (it + 1 < ntile) {
            int q = p ^ 1;
            *(uint4*)&As[q][sidx]     = make_uint4(f2tf(na0.x), f2tf(na0.y), f2tf(na0.z), f2tf(na0.w));
            *(uint4*)&As[q][sidx + 4] = make_uint4(f2tf(na1.x), f2tf(na1.y), f2tf(na1.z), f2tf(na1.w));
            Bs[q][(bc0 + 0) * SPAD + bk0] = f2tf(nv0.x);
            Bs[q][(bc0 + 1) * SPAD + bk0] = f2tf(nv0.y);
            Bs[q][(bc0 + 2) * SPAD + bk0] = f2tf(nv0.z);
            Bs[q][(bc0 + 3) * SPAD + bk0] = f2tf(nv0.w);
            Bs[q][(bc1 + 0) * SPAD + bk1] = f2tf(nv1.x);
            Bs[q][(bc1 + 1) * SPAD + bk1] = f2tf(nv1.y);
            Bs[q][(bc1 + 2) * SPAD + bk1] = f2tf(nv1.z);
            Bs[q][(bc1 + 3) * SPAD + bk1] = f2tf(nv1.w);
        }
        __syncthreads();
        p ^= 1;
    }

#pragma unroll
    for (int mt = 0; mt < 2; mt++) {
#pragma unroll
        for (int nt = 0; nt < 4; nt++) {
            int col = n0 + wn + nt * 8 + 2 * tg;
            int row = m0 + wm + mt * 16 + g;
            float2 v0, v1;
            v0.x = acc[mt][nt][0]; v0.y = acc[mt][nt][1];
            v1.x = acc[mt][nt][2]; v1.y = acc[mt][nt][3];
            *(float2*)&C[(long long)row * ldc + col] = v0;
            *(float2*)&C[(long long)(row + 8) * ldc + col] = v1;
        }
    }
}

// ---------------- row softmax ----------------
__global__ void softmax_rows(float* __restrict__ S, int n) {
    float* row = S + (long long)blockIdx.x * n;
    __shared__ float red[128];
    int tid = threadIdx.x;
    float m = -1e30f;
    for (int j = tid; j < n; j += 128) m = fmaxf(m, row[j]);
    red[tid] = m; __syncthreads();
    for (int off = 64; off; off >>= 1) {
        if (tid < off) red[tid] = fmaxf(red[tid], red[tid + off]);
        __syncthreads();
    }
    m = red[0]; __syncthreads();
    float s = 0.f;
    for (int j = tid; j < n; j += 128) { float e = expf(row[j] - m); row[j] = e; s += e; }
    red[tid] = s; __syncthreads();
    for (int off = 64; off; off >>= 1) {
        if (tid < off) red[tid] += red[tid + off];
        __syncthreads();
    }
    float inv = 1.0f / red[0];
    for (int j = tid; j < n; j += 128) row[j] *= inv;
}

// ---------------- x = LN(x + delta) ----------------
__global__ void ln_res_kernel(float* __restrict__ x, const float* __restrict__ delta,
                              const float* __restrict__ s, const float* __restrict__ b, int d) {
    float* xr = x + (long long)blockIdx.x * d;
    const float* dr = delta + (long long)blockIdx.x * d;
    __shared__ float red[256];
    int tid = threadIdx.x;
    float sum = 0.f;
    for (int j = tid; j < d; j += 256) { float v = xr[j] + dr[j]; xr[j] = v; sum += v; }
    red[tid] = sum; __syncthreads();
    for (int off = 128; off; off >>= 1) {
        if (tid < off) red[tid] += red[tid + off];
        __syncthreads();
    }
    float mean = red[0] / d; __syncthreads();
    float s2 = 0.f;
    for (int j = tid; j < d; j += 256) { float v = xr[j] - mean; s2 += v * v; }
    red[tid] = s2; __syncthreads();
    for (int off = 128; off; off >>= 1) {
        if (tid < off) red[tid] += red[tid + off];
        __syncthreads();
    }
    float inv = rsqrtf(red[0] / d + 1e-5f);
    __syncthreads();
    for (int j = tid; j < d; j += 256) xr[j] = (xr[j] - mean) * inv * s[j] + b[j];
}

// ---------------- final linear ----------------
__global__ void lin_kernel(const float* __restrict__ x, const float* __restrict__ w,
                           const float* __restrict__ b, float* __restrict__ a,
                           float* __restrict__ c) {
    int i = blockIdx.x;
    const float* xr = x + (long long)i * CDIM;
    __shared__ float red[4][256];
    int tid = threadIdx.x;
    float s0 = 0, s1 = 0, s2 = 0, s3 = 0;
    for (int k = tid; k < CDIM; k += 256) {
        float xv = xr[k];
        s0 += xv * w[k];
        s1 += xv * w[2 * CDIM + k];
        s2 += xv * w[CDIM + k];
        s3 += xv * w[2 * CDIM + CDIM + k];
    }
    red[0][tid] = s0; red[1][tid] = s1; red[2][tid] = s2; red[3][tid] = s3;
    __syncthreads();
    for (int off = 128; off; off >>= 1) {
        if (tid < off) {
            red[0][tid] += red[0][tid + off];
            red[1][tid] += red[1][tid + off];
            red[2][tid] += red[2][tid + off];
            red[3][tid] += red[3][tid + off];
        }
        __syncthreads();
    }
    if (tid == 0) {
        a[2 * i]     = red[0][0] + b[0];
        a[2 * i + 1] = red[1][0] + b[1];
        c[2 * i]     = red[2][0];
        c[2 * i + 1] = red[3][0];
    }
}

// ---------------- pairwise probs + per-row loss partials ----------------
__global__ void pair_kernel(const float* __restrict__ a, const float* __restrict__ c,
                            const int* __restrict__ gt, float* __restrict__ probs,
                            float* __restrict__ rowcell, float* __restrict__ rowlink) {
    int i = blockIdx.x, j = threadIdx.x;
    float l0 = a[2 * i] + c[2 * j];
    float l1 = a[2 * i + 1] + c[2 * j + 1];
    float m = fmaxf(l0, l1);
    float e0 = expf(l0 - m), e1 = expf(l1 - m);
    float inv = 1.0f / (e0 + e1);
    float p0 = e0 * inv, p1 = e1 * inv;
    long long idx = ((long long)i * N_TOK + j) * 2;
    probs[idx] = p0; probs[idx + 1] = p1;
    float mm = fmaxf(p0, p1);
    float lse = mm + logf(expf(p0 - mm) + expf(p1 - mm));
    float pg = gt[i * N_TOK + j] ? p1 : p0;
    float cell = lse - pg;

    __shared__ float red[512];
    red[j] = cell;
    if (j < 128) red[384 + j] = 0.f;
    __syncthreads();
    for (int off = 256; off; off >>= 1) {
        if (j < off) red[j] += red[j + off];
        __syncthreads();
    }
    if (j == 0) rowcell[i] = red[0];
    __syncthreads();
    red[j] = p1;
    if (j < 128) red[384 + j] = 0.f;
    __syncthreads();
    for (int off = 256; off; off >>= 1) {
        if (j < off) red[j] += red[j + off];
        __syncthreads();
    }
    if (j == 0) rowlink[i] = red[0];
}

__global__ void col_kernel(const float* __restrict__ probs, float* __restrict__ collink) {
    int j = blockIdx.x; int tid = threadIdx.x;
    float s = 0.f;
    for (int i = tid; i < N_TOK; i += 128) s += probs[((long long)i * N_TOK + j) * 2 + 1];
    __shared__ float red[128];
    red[tid] = s; __syncthreads();
    for (int off = 64; off; off >>= 1) {
        if (tid < off) red[tid] += red[tid + off];
        __syncthreads();
    }
    if (tid == 0) collink[j] = red[0];
}

__global__ void final_kernel(const float* __restrict__ rowcell, const float* __restrict__ rowlink,
                             const float* __restrict__ collink, float* __restrict__ out,
                             int out_size) {
    __shared__ float r1[512], r2[512];
    int tid = threadIdx.x;
    r1[tid] = (tid < N_TOK) ? rowcell[tid] : 0.f;
    r2[tid] = (tid < N_TOK - 1) ? fabsf(rowlink[tid] + collink[tid] - 1.0f) : 0.f;
    __syncthreads();
    for (int off = 256; off; off >>= 1) {
        if (tid < off) { r1[tid] += r1[tid + off]; r2[tid] += r2[tid + off]; }
        __syncthreads();
    }
    if (tid == 0 && out_size >= N_TOK * N_TOK * 2 + 2) {
        out[N_TOK * N_TOK * 2]     = r1[0] / (float)N_TOK;
        out[N_TOK * N_TOK * 2 + 1] = r2[0];
    }
}

// ---------------- host orchestration ----------------
struct EncWeights {
    const float *qkv_w, *qkv_b, *out_w, *out_b, *ln1_s, *ln1_b;
    const float *ff1_w, *ff1_b, *ff2_w, *ff2_b, *ln2_s, *ln2_b;
};

static void run_encoder(float* x, int d, const EncWeights& w,
                        float* qkv, float* sc, float* o, float* y, float* h) {
    const int M = N_TOK;
    const int hd = d / NH;
    const float scale = 1.0f / sqrtf((float)hd);
    for (int l = 0; l < NLAYERS; l++) {
        const float* Wq = w.qkv_w + (long long)l * 3 * d * d;
        const float* Bq = w.qkv_b + (long long)l * 3 * d;
        // qkv = x @ Wq^T + Bq
        tf32_nt<<<dim3(3 * d / 64, M / 64, 1), 128>>>(
            x, d, 0, Wq, d, 0, Bq, qkv, 3 * d, 0, d, 1.f, 0);
        // scores[h] = Q_h @ K_h^T * scale (batched over heads)
        tf32_nt<<<dim3(M / 64, M / 64, NH), 128>>>(
            qkv, 3 * d, hd, qkv + d, 3 * d, hd, nullptr,
            sc, M, (long long)M * M, hd, scale, 0);
        softmax_rows<<<NH * M, 128>>>(sc, M);
        // o[:, h*hd:] = attn_h @ V_h (batched)
        tf32_nn<<<dim3(hd / 64, M / 64, NH), 128>>>(
            sc, M, (long long)M * M, qkv + 2 * d, 3 * d, hd,
            o, d, hd, M);
        // y = o @ out_w^T + out_b
        tf32_nt<<<dim3(d / 64, M / 64, 1), 128>>>(
            o, d, 0, w.out_w + (long long)l * d * d, d, 0, w.out_b + (long long)l * d,
            y, d, 0, d, 1.f, 0);
        ln_res_kernel<<<M, 256>>>(x, y, w.ln1_s + (long long)l * d, w.ln1_b + (long long)l * d, d);
        // h = relu(x @ ff1^T + b1)
        tf32_nt<<<dim3(FF_DIM / 64, M / 64, 1), 128>>>(
            x, d, 0, w.ff1_w + (long long)l * FF_DIM * d, d, 0, w.ff1_b + (long long)l * FF_DIM,
            h, FF_DIM, 0, d, 1.f, 1);
        // y = h @ ff2^T + b2
        tf32_nt<<<dim3(d / 64, M / 64, 1), 128>>>(
            h, FF_DIM, 0, w.ff2_w + (long long)l * d * FF_DIM, FF_DIM, 0, w.ff2_b + (long long)l * d,
            y, d, 0, FF_DIM, 1.f, 0);
        ln_res_kernel<<<M, 256>>>(x, y, w.ln2_s + (long long)l * d, w.ln2_b + (long long)l * d, d);
    }
}

extern "C" void kernel_launch(void* const* d_in, const int* in_sizes, int n_in,
                              void* d_out, int out_size) {
    const float* text   = (const float*)d_in[0];
    const float* vision = (const float*)d_in[1];
    const int*   gt     = (const int*)d_in[2];

    EncWeights tw = {
        (const float*)d_in[3],  (const float*)d_in[4],  (const float*)d_in[5],
        (const float*)d_in[6],  (const float*)d_in[7],  (const float*)d_in[8],
        (const float*)d_in[9],  (const float*)d_in[10], (const float*)d_in[11],
        (const float*)d_in[12], (const float*)d_in[13], (const float*)d_in[14]
    };
    EncWeights cw = {
        (const float*)d_in[15], (const float*)d_in[16], (const float*)d_in[17],
        (const float*)d_in[18], (const float*)d_in[19], (const float*)d_in[20],
        (const float*)d_in[21], (const float*)d_in[22], (const float*)d_in[23],
        (const float*)d_in[24], (const float*)d_in[25], (const float*)d_in[26]
    };
    const float* lin_w = (const float*)d_in[27];
    const float* lin_b = (const float*)d_in[28];

    float* buf = nullptr;
    cudaGetSymbolAddress((void**)&buf, g_buf);
    float* x    = buf + OFF_X;
    float* x2   = buf + OFF_X2;
    float* qkv  = buf + OFF_QKV;
    float* sc   = buf + OFF_SC;
    float* o    = buf + OFF_O;
    float* y    = buf + OFF_Y;
    float* h    = buf + OFF_H;
    float* ga   = buf + OFF_A;
    float* gc   = buf + OFF_C;
    float* rcel = buf + OFF_RC;
    float* rlnk = buf + OFF_RL;
    float* clnk = buf + OFF_CL;

    copy_k<<<(N_TOK * TDIM + 255) / 256, 256>>>(x, text, N_TOK * TDIM);
    run_encoder(x, TDIM, tw, qkv, sc, o, y, h);

    concat_k<<<(N_TOK * CDIM + 255) / 256, 256>>>(x2, x, vision);
    run_encoder(x2, CDIM, cw, qkv, sc, o, y, h);

    lin_kernel<<<N_TOK, 256>>>(x2, lin_w, lin_b, ga, gc);

    float* out = (float*)d_out;
    pair_kernel<<<N_TOK, N_TOK>>>(ga, gc, gt, out, rcel, rlnk);
    col_kernel<<<N_TOK, 128>>>(out, clnk);
    final_kernel<<<1, 512>>>(rcel, rlnk, clnk, out, out_size);
}

// round 3
// speedup vs baseline: 2.2594x; 1.4465x over previous
#include <cuda_runtime.h>
#include <math.h>

#define N_TOK 384
#define TDIM 768
#define VDIM 768
#define CDIM 1536
#define FF_DIM 2048
#define NH 4
#define NLAYERS 2

// ---------------- scratch (no allocations allowed) ----------------
#define OFF_X   0LL
#define OFF_X2  589824LL
#define OFF_QKV 1179648LL
#define OFF_SC  2949120LL
#define OFF_O   3538944LL
#define OFF_Y   4128768LL
#define OFF_H   4718592LL
#define OFF_A   5505024LL
#define OFF_C   5505792LL
#define OFF_RC  5506560LL
#define OFF_RL  5506944LL
#define OFF_CL  5507328LL
#define BUF_TOTAL 5507712LL

__device__ float g_buf[BUF_TOTAL];

// ---------------- helpers ----------------
__device__ __forceinline__ unsigned f2tf(float x) {
    unsigned u;
    asm("cvt.rna.tf32.f32 %0, %1;" : "=r"(u) : "f"(x));
    return u;
}

__device__ __forceinline__ void mma8(float* c, const unsigned* a, const unsigned* b) {
    asm volatile(
        "mma.sync.aligned.m16n8k8.row.col.f32.tf32.tf32.f32 "
        "{%0,%1,%2,%3},{%4,%5,%6,%7},{%8,%9},{%0,%1,%2,%3};"
        : "+f"(c[0]), "+f"(c[1]), "+f"(c[2]), "+f"(c[3])
        : "r"(a[0]), "r"(a[1]), "r"(a[2]), "r"(a[3]), "r"(b[0]), "r"(b[1]));
}

__device__ __forceinline__ void cpa16(unsigned dst, const float* src) {
    asm volatile("cp.async.cg.shared.global [%0], [%1], 16;" :: "r"(dst), "l"(src));
}
__device__ __forceinline__ void cpa_commit() {
    asm volatile("cp.async.commit_group;");
}
template <int N>
__device__ __forceinline__ void cpa_wait() {
    asm volatile("cp.async.wait_group %0;" :: "n"(N));
}

__global__ void copy_k(float* __restrict__ dst, const float* __restrict__ src, int n) {
    int i = blockIdx.x * blockDim.x + threadIdx.x;
    if (i < n) dst[i] = src[i];
}

__global__ void concat_k(float* __restrict__ dst, const float* __restrict__ te,
                         const float* __restrict__ vis) {
    int i = blockIdx.x * blockDim.x + threadIdx.x;
    if (i < N_TOK * CDIM) {
        int r = i / CDIM, c = i % CDIM;
        dst[i] = (c < TDIM) ? te[r * TDIM + c] : vis[r * VDIM + (c - TDIM)];
    }
}

// ============ NT GEMM: C = alpha*A(MxK,row)@W(NxK,row)^T + bias =============
// 64x128 block tile, BK=16, 256 threads = 8 warps (2x4), warp tile 32x32.
// 3-stage cp.async pipeline, raw fp32 bits fed to tf32 MMA (HW truncation).
#define SPAD 20
#define NT_AS (64 * SPAD)
#define NT_BS (128 * SPAD)

__global__ void __launch_bounds__(256) tf32_nt(
    const float* __restrict__ A, int lda, long long aZ,
    const float* __restrict__ W, int ldw, long long wZ,
    const float* __restrict__ Bias,
    float* __restrict__ C, int ldc, long long cZ,
    int K, float alpha, int relu)
{
    A += blockIdx.z * aZ; W += blockIdx.z * wZ; C += blockIdx.z * cZ;
    __shared__ float As[3][NT_AS];
    __shared__ float Bs[3][NT_BS];

    int tid = threadIdx.x;
    int warp = tid >> 5, lane = tid & 31;
    int g = lane >> 2, tg = lane & 3;
    int wm = (warp >> 2) * 32, wn = (warp & 3) * 32;
    int m0 = blockIdx.y * 64, n0 = blockIdx.x * 128;

    // cp.async mapping: each thread moves 3x16B per stage.
    int lrow = tid >> 2;            // 0..63
    int q4   = (tid & 3) * 4;       // 0,4,8,12
    const float* aSrc  = A + (long long)(m0 + lrow) * lda + q4;
    const float* bSrc0 = W + (long long)(n0 + lrow) * ldw + q4;
    const float* bSrc1 = W + (long long)(n0 + 64 + lrow) * ldw + q4;
    unsigned aDstBase  = (unsigned)__cvta_generic_to_shared(&As[0][lrow * SPAD + q4]);
    unsigned bDst0Base = (unsigned)__cvta_generic_to_shared(&Bs[0][lrow * SPAD + q4]);
    unsigned bDst1Base = (unsigned)__cvta_generic_to_shared(&Bs[0][(64 + lrow) * SPAD + q4]);

    int ntile = K / 16;
    float acc[2][4][4] = {};

    // prologue: stages 0 and 1
#pragma unroll
    for (int s = 0; s < 2; s++) {
        int k0 = s * 16;
        cpa16(aDstBase  + s * NT_AS * 4, aSrc  + k0);
        cpa16(bDst0Base + s * NT_BS * 4, bSrc0 + k0);
        cpa16(bDst1Base + s * NT_BS * 4, bSrc1 + k0);
        cpa_commit();
    }

    for (int it = 0; it < ntile; it++) {
        cpa_wait<1>();
        __syncthreads();
        // issue stage it+2
        if (it + 2 < ntile) {
            int s = (it + 2) % 3;
            int k0 = (it + 2) * 16;
            cpa16(aDstBase  + s * NT_AS * 4, aSrc  + k0);
            cpa16(bDst0Base + s * NT_BS * 4, bSrc0 + k0);
            cpa16(bDst1Base + s * NT_BS * 4, bSrc1 + k0);
        }
        cpa_commit();
        // compute stage it
        const unsigned* Ab = (const unsigned*)As[it % 3];
        const unsigned* Bb = (const unsigned*)Bs[it % 3];
#pragma unroll
        for (int ks = 0; ks < 2; ks++) {
            int kb = ks * 8;
            unsigned a[2][4], b[4][2];
#pragma unroll
            for (int mt = 0; mt < 2; mt++) {
                const unsigned* base = &Ab[(wm + mt * 16 + g) * SPAD + kb + tg];
                a[mt][0] = base[0];
                a[mt][1] = base[8 * SPAD];
                a[mt][2] = base[4];
                a[mt][3] = base[8 * SPAD + 4];
            }
#pragma unroll
            for (int nt = 0; nt < 4; nt++) {
                const unsigned* base = &Bb[(wn + nt * 8 + g) * SPAD + kb + tg];
                b[nt][0] = base[0];
                b[nt][1] = base[4];
            }
#pragma unroll
            for (int mt = 0; mt < 2; mt++)
#pragma unroll
                for (int nt = 0; nt < 4; nt++)
                    mma8(acc[mt][nt], a[mt], b[nt]);
        }
    }

#pragma unroll
    for (int mt = 0; mt < 2; mt++) {
#pragma unroll
        for (int nt = 0; nt < 4; nt++) {
            int col = n0 + wn + nt * 8 + 2 * tg;
            float b0 = 0.f, b1 = 0.f;
            if (Bias) { b0 = Bias[col]; b1 = Bias[col + 1]; }
            int row = m0 + wm + mt * 16 + g;
            float2 v0, v1;
            v0.x = acc[mt][nt][0] * alpha + b0;
            v0.y = acc[mt][nt][1] * alpha + b1;
            v1.x = acc[mt][nt][2] * alpha + b0;
            v1.y = acc[mt][nt][3] * alpha + b1;
            if (relu) {
                v0.x = fmaxf(v0.x, 0.f); v0.y = fmaxf(v0.y, 0.f);
                v1.x = fmaxf(v1.x, 0.f); v1.y = fmaxf(v1.y, 0.f);
            }
            *(float2*)&C[(long long)row * ldc + col] = v0;
            *(float2*)&C[(long long)(row + 8) * ldc + col] = v1;
        }
    }
}

// ============ NN GEMM: C = A(MxK,row) @ B(KxN,row), batched via z ============
// 64x64 tile, BK=16, 128 threads (small attn*V GEMM only).
__global__ void __launch_bounds__(128) tf32_nn(
    const float* __restrict__ A, int lda, long long aZ,
    const float* __restrict__ B, int ldb, long long bZ,
    float* __restrict__ C, int ldc, long long cZ,
    int K)
{
    A += blockIdx.z * aZ; B += blockIdx.z * bZ; C += blockIdx.z * cZ;
    __shared__ unsigned As[2][64 * SPAD];
    __shared__ unsigned Bs[2][64 * SPAD];
    int tid = threadIdx.x;
    int warp = tid >> 5, lane = tid & 31;
    int g = lane >> 2, tg = lane & 3;
    int wm = (warp >> 1) * 32, wn = (warp & 1) * 32;
    int m0 = blockIdx.y * 64, n0 = blockIdx.x * 64;

    int lrow = tid >> 1;
    int lcol = (tid & 1) * 8;
    const float* Ap = A + (long long)(m0 + lrow) * lda + lcol;
    int sidx = lrow * SPAD + lcol;

    int f0 = tid * 2;
    int bk0 = f0 >> 4, bc0 = (f0 & 15) * 4;
    int bk1 = (f0 + 1) >> 4, bc1 = ((f0 + 1) & 15) * 4;
    const float* Bp0 = B + (long long)bk0 * ldb + n0 + bc0;
    const float* Bp1 = B + (long long)bk1 * ldb + n0 + bc1;

    float acc[2][4][4] = {};
    int ntile = K / 16;
    {
        float4 a0 = *(const float4*)(Ap);
        float4 a1 = *(const float4*)(Ap + 4);
        float4 v0 = *(const float4*)(Bp0);
        float4 v1 = *(const float4*)(Bp1);
        *(uint4*)&As[0][sidx]     = make_uint4(f2tf(a0.x), f2tf(a0.y), f2tf(a0.z), f2tf(a0.w));
        *(uint4*)&As[0][sidx + 4] = make_uint4(f2tf(a1.x), f2tf(a1.y), f2tf(a1.z), f2tf(a1.w));
        Bs[0][(bc0 + 0) * SPAD + bk0] = f2tf(v0.x);
        Bs[0][(bc0 + 1) * SPAD + bk0] = f2tf(v0.y);
        Bs[0][(bc0 + 2) * SPAD + bk0] = f2tf(v0.z);
        Bs[0][(bc0 + 3) * SPAD + bk0] = f2tf(v0.w);
        Bs[0][(bc1 + 0) * SPAD + bk1] = f2tf(v1.x);
        Bs[0][(bc1 + 1) * SPAD + bk1] = f2tf(v1.y);
        Bs[0][(bc1 + 2) * SPAD + bk1] = f2tf(v1.z);
        Bs[0][(bc1 + 3) * SPAD + bk1] = f2tf(v1.w);
    }
    __syncthreads();
    int p = 0;
    for (int it = 0; it < ntile; it++) {
        float4 na0, na1, nv0, nv1;
        if (it + 1 < ntile) {
            int ko = (it + 1) * 16;
            na0 = *(const float4*)(Ap + ko);
            na1 = *(const float4*)(Ap + ko + 4);
            nv0 = *(const float4*)(Bp0 + (long long)ko * ldb);
            nv1 = *(const float4*)(Bp1 + (long long)ko * ldb);
        }
#pragma unroll
        for (int ks = 0; ks < 2; ks++) {
            int kb = ks * 8;
            unsigned a[2][4], b[4][2];
#pragma unroll
            for (int mt = 0; mt < 2; mt++) {
                const unsigned* base = &As[p][(wm + mt * 16 + g) * SPAD + kb + tg];
                a[mt][0] = base[0];
                a[mt][1] = base[8 * SPAD];
                a[mt][2] = base[4];
                a[mt][3] = base[8 * SPAD + 4];
            }
#pragma unroll
            for (int nt = 0; nt < 4; nt++) {
                const unsigned* base = &Bs[p][(wn + nt * 8 + g) * SPAD + kb + tg];
                b[nt][0] = base[0];
                b[nt][1] = base[4];
            }
#pragma unroll
            for (int mt = 0; mt < 2; mt++)
#pragma unroll
                for (int nt = 0; nt < 4; nt++)
                    mma8(acc[mt][nt], a[mt], b[nt]);
        }
        if (it + 1 < ntile) {
            int q = p ^ 1;
            *(uint4*)&As[q][sidx]     = make_uint4(f2tf(na0.x), f2tf(na0.y), f2tf(na0.z), f2tf(na0.w));
            *(uint4*)&As[q][sidx + 4] = make_uint4(f2tf(na1.x), f2tf(na1.y), f2tf(na1.z), f2tf(na1.w));
            Bs[q][(bc0 + 0) * SPAD + bk0] = f2tf(nv0.x);
            Bs[q][(bc0 + 1) * SPAD + bk0] = f2tf(nv0.y);
            Bs[q][(bc0 + 2) * SPAD + bk0] = f2tf(nv0.z);
            Bs[q][(bc0 + 3) * SPAD + bk0] = f2tf(nv0.w);
            Bs[q][(bc1 + 0) * SPAD + bk1] = f2tf(nv1.x);
            Bs[q][(bc1 + 1) * SPAD + bk1] = f2tf(nv1.y);
            Bs[q][(bc1 + 2) * SPAD + bk1] = f2tf(nv1.z);
            Bs[q][(bc1 + 3) * SPAD + bk1] = f2tf(nv1.w);
        }
        __syncthreads();
        p ^= 1;
    }

#pragma unroll
    for (int mt = 0; mt < 2; mt++) {
#pragma unroll
        for (int nt = 0; nt < 4; nt++) {
            int col = n0 + wn + nt * 8 + 2 * tg;
            int row = m0 + wm + mt * 16 + g;
            float2 v0, v1;
            v0.x = acc[mt][nt][0]; v0.y = acc[mt][nt][1];
            v1.x = acc[mt][nt][2]; v1.y = acc[mt][nt][3];
            *(float2*)&C[(long long)row * ldc + col] = v0;
            *(float2*)&C[(long long)(row + 8) * ldc + col] = v1;
        }
    }
}

// ---------------- row softmax ----------------
__global__ void softmax_rows(float* __restrict__ S, int n) {
    float* row = S + (long long)blockIdx.x * n;
    __shared__ float red[128];
    int tid = threadIdx.x;
    float m = -1e30f;
    for (int j = tid; j < n; j += 128) m = fmaxf(m, row[j]);
    red[tid] = m; __syncthreads();
    for (int off = 64; off; off >>= 1) {
        if (tid < off) red[tid] = fmaxf(red[tid], red[tid + off]);
        __syncthreads();
    }
    m = red[0]; __syncthreads();
    float s = 0.f;
    for (int j = tid; j < n; j += 128) { float e = expf(row[j] - m); row[j] = e; s += e; }
    red[tid] = s; __syncthreads();
    for (int off = 64; off; off >>= 1) {
        if (tid < off) red[tid] += red[tid + off];
        __syncthreads();
    }
    float inv = 1.0f / red[0];
    for (int j = tid; j < n; j += 128) row[j] *= inv;
}

// ---------------- x = LN(x + delta) ----------------
__global__ void ln_res_kernel(float* __restrict__ x, const float* __restrict__ delta,
                              const float* __restrict__ s, const float* __restrict__ b, int d) {
    float* xr = x + (long long)blockIdx.x * d;
    const float* dr = delta + (long long)blockIdx.x * d;
    __shared__ float red[256];
    int tid = threadIdx.x;
    float sum = 0.f;
    for (int j = tid; j < d; j += 256) { float v = xr[j] + dr[j]; xr[j] = v; sum += v; }
    red[tid] = sum; __syncthreads();
    for (int off = 128; off; off >>= 1) {
        if (tid < off) red[tid] += red[tid + off];
        __syncthreads();
    }
    float mean = red[0] / d; __syncthreads();
    float s2 = 0.f;
    for (int j = tid; j < d; j += 256) { float v = xr[j] - mean; s2 += v * v; }
    red[tid] = s2; __syncthreads();
    for (int off = 128; off; off >>= 1) {
        if (tid < off) red[tid] += red[tid + off];
        __syncthreads();
    }
    float inv = rsqrtf(red[0] / d + 1e-5f);
    __syncthreads();
    for (int j = tid; j < d; j += 256) xr[j] = (xr[j] - mean) * inv * s[j] + b[j];
}

// ---------------- final linear ----------------
__global__ void lin_kernel(const float* __restrict__ x, const float* __restrict__ w,
                           const float* __restrict__ b, float* __restrict__ a,
                           float* __restrict__ c) {
    int i = blockIdx.x;
    const float* xr = x + (long long)i * CDIM;
    __shared__ float red[4][256];
    int tid = threadIdx.x;
    float s0 = 0, s1 = 0, s2 = 0, s3 = 0;
    for (int k = tid; k < CDIM; k += 256) {
        float xv = xr[k];
        s0 += xv * w[k];
        s1 += xv * w[2 * CDIM + k];
        s2 += xv * w[CDIM + k];
        s3 += xv * w[2 * CDIM + CDIM + k];
    }
    red[0][tid] = s0; red[1][tid] = s1; red[2][tid] = s2; red[3][tid] = s3;
    __syncthreads();
    for (int off = 128; off; off >>= 1) {
        if (tid < off) {
            red[0][tid] += red[0][tid + off];
            red[1][tid] += red[1][tid + off];
            red[2][tid] += red[2][tid + off];
            red[3][tid] += red[3][tid + off];
        }
        __syncthreads();
    }
    if (tid == 0) {
        a[2 * i]     = red[0][0] + b[0];
        a[2 * i + 1] = red[1][0] + b[1];
        c[2 * i]     = red[2][0];
        c[2 * i + 1] = red[3][0];
    }
}

// ---------------- pairwise probs + per-row loss partials ----------------
__global__ void pair_kernel(const float* __restrict__ a, const float* __restrict__ c,
                            const int* __restrict__ gt, float* __restrict__ probs,
                            float* __restrict__ rowcell, float* __restrict__ rowlink) {
    int i = blockIdx.x, j = threadIdx.x;
    float l0 = a[2 * i] + c[2 * j];
    float l1 = a[2 * i + 1] + c[2 * j + 1];
    float m = fmaxf(l0, l1);
    float e0 = expf(l0 - m), e1 = expf(l1 - m);
    float inv = 1.0f / (e0 + e1);
    float p0 = e0 * inv, p1 = e1 * inv;
    long long idx = ((long long)i * N_TOK + j) * 2;
    probs[idx] = p0; probs[idx + 1] = p1;
    float mm = fmaxf(p0, p1);
    float lse = mm + logf(expf(p0 - mm) + expf(p1 - mm));
    float pg = gt[i * N_TOK + j] ? p1 : p0;
    float cell = lse - pg;

    __shared__ float red[512];
    red[j] = cell;
    if (j < 128) red[384 + j] = 0.f;
    __syncthreads();
    for (int off = 256; off; off >>= 1) {
        if (j < off) red[j] += red[j + off];
        __syncthreads();
    }
    if (j == 0) rowcell[i] = red[0];
    __syncthreads();
    red[j] = p1;
    if (j < 128) red[384 + j] = 0.f;
    __syncthreads();
    for (int off = 256; off; off >>= 1) {
        if (j < off) red[j] += red[j + off];
        __syncthreads();
    }
    if (j == 0) rowlink[i] = red[0];
}

__global__ void col_kernel(const float* __restrict__ probs, float* __restrict__ collink) {
    int j = blockIdx.x; int tid = threadIdx.x;
    float s = 0.f;
    for (int i = tid; i < N_TOK; i += 128) s += probs[((long long)i * N_TOK + j) * 2 + 1];
    __shared__ float red[128];
    red[tid] = s; __syncthreads();
    for (int off = 64; off; off >>= 1) {
        if (tid < off) red[tid] += red[tid + off];
        __syncthreads();
    }
    if (tid == 0) collink[j] = red[0];
}

__global__ void final_kernel(const float* __restrict__ rowcell, const float* __restrict__ rowlink,
                             const float* __restrict__ collink, float* __restrict__ out,
                             int out_size) {
    __shared__ float r1[512], r2[512];
    int tid = threadIdx.x;
    r1[tid] = (tid < N_TOK) ? rowcell[tid] : 0.f;
    r2[tid] = (tid < N_TOK - 1) ? fabsf(rowlink[tid] + collink[tid] - 1.0f) : 0.f;
    __syncthreads();
    for (int off = 256; off; off >>= 1) {
        if (tid < off) { r1[tid] += r1[tid + off]; r2[tid] += r2[tid + off]; }
        __syncthreads();
    }
    if (tid == 0 && out_size >= N_TOK * N_TOK * 2 + 2) {
        out[N_TOK * N_TOK * 2]     = r1[0] / (float)N_TOK;
        out[N_TOK * N_TOK * 2 + 1] = r2[0];
    }
}

// ---------------- host orchestration ----------------
struct EncWeights {
    const float *qkv_w, *qkv_b, *out_w, *out_b, *ln1_s, *ln1_b;
    const float *ff1_w, *ff1_b, *ff2_w, *ff2_b, *ln2_s, *ln2_b;
};

static void run_encoder(float* x, int d, const EncWeights& w,
                        float* qkv, float* sc, float* o, float* y, float* h) {
    const int M = N_TOK;
    const int hd = d / NH;
    const float scale = 1.0f / sqrtf((float)hd);
    for (int l = 0; l < NLAYERS; l++) {
        const float* Wq = w.qkv_w + (long long)l * 3 * d * d;
        const float* Bq = w.qkv_b + (long long)l * 3 * d;
        // qkv = x @ Wq^T + Bq
        tf32_nt<<<dim3(3 * d / 128, M / 64, 1), 256>>>(
            x, d, 0, Wq, d, 0, Bq, qkv, 3 * d, 0, d, 1.f, 0);
        // scores[h] = Q_h @ K_h^T * scale (batched over heads)
        tf32_nt<<<dim3(M / 128, M / 64, NH), 256>>>(
            qkv, 3 * d, hd, qkv + d, 3 * d, hd, nullptr,
            sc, M, (long long)M * M, hd, scale, 0);
        softmax_rows<<<NH * M, 128>>>(sc, M);
        // o[:, h*hd:] = attn_h @ V_h (batched)
        tf32_nn<<<dim3(hd / 64, M / 64, NH), 128>>>(
            sc, M, (long long)M * M, qkv + 2 * d, 3 * d, hd,
            o, d, hd, M);
        // y = o @ out_w^T + out_b
        tf32_nt<<<dim3(d / 128, M / 64, 1), 256>>>(
            o, d, 0, w.out_w + (long long)l * d * d, d, 0, w.out_b + (long long)l * d,
            y, d, 0, d, 1.f, 0);
        ln_res_kernel<<<M, 256>>>(x, y, w.ln1_s + (long long)l * d, w.ln1_b + (long long)l * d, d);
        // h = relu(x @ ff1^T + b1)
        tf32_nt<<<dim3(FF_DIM / 128, M / 64, 1), 256>>>(
            x, d, 0, w.ff1_w + (long long)l * FF_DIM * d, d, 0, w.ff1_b + (long long)l * FF_DIM,
            h, FF_DIM, 0, d, 1.f, 1);
        // y = h @ ff2^T + b2
        tf32_nt<<<dim3(d / 128, M / 64, 1), 256>>>(
            h, FF_DIM, 0, w.ff2_w + (long long)l * d * FF_DIM, FF_DIM, 0, w.ff2_b + (long long)l * d,
            y, d, 0, FF_DIM, 1.f, 0);
        ln_res_kernel<<<M, 256>>>(x, y, w.ln2_s + (long long)l * d, w.ln2_b + (long long)l * d, d);
    }
}

extern "C" void kernel_launch(void* const* d_in, const int* in_sizes, int n_in,
                              void* d_out, int out_size) {
    const float* text   = (const float*)d_in[0];
    const float* vision = (const float*)d_in[1];
    const int*   gt     = (const int*)d_in[2];

    EncWeights tw = {
        (const float*)d_in[3],  (const float*)d_in[4],  (const float*)d_in[5],
        (const float*)d_in[6],  (const float*)d_in[7],  (const float*)d_in[8],
        (const float*)d_in[9],  (const float*)d_in[10], (const float*)d_in[11],
        (const float*)d_in[12], (const float*)d_in[13], (const float*)d_in[14]
    };
    EncWeights cw = {
        (const float*)d_in[15], (const float*)d_in[16], (const float*)d_in[17],
        (const float*)d_in[18], (const float*)d_in[19], (const float*)d_in[20],
        (const float*)d_in[21], (const float*)d_in[22], (const float*)d_in[23],
        (const float*)d_in[24], (const float*)d_in[25], (const float*)d_in[26]
    };
    const float* lin_w = (const float*)d_in[27];
    const float* lin_b = (const float*)d_in[28];

    float* buf = nullptr;
    cudaGetSymbolAddress((void**)&buf, g_buf);
    float* x    = buf + OFF_X;
    float* x2   = buf + OFF_X2;
    float* qkv  = buf + OFF_QKV;
    float* sc   = buf + OFF_SC;
    float* o    = buf + OFF_O;
    float* y    = buf + OFF_Y;
    float* h    = buf + OFF_H;
    float* ga   = buf + OFF_A;
    float* gc   = buf + OFF_C;
    float* rcel = buf + OFF_RC;
    float* rlnk = buf + OFF_RL;
    float* clnk = buf + OFF_CL;

    copy_k<<<(N_TOK * TDIM + 255) / 256, 256>>>(x, text, N_TOK * TDIM);
    run_encoder(x, TDIM, tw, qkv, sc, o, y, h);

    concat_k<<<(N_TOK * CDIM + 255) / 256, 256>>>(x2, x, vision);
    run_encoder(x2, CDIM, cw, qkv, sc, o, y, h);

    lin_kernel<<<N_TOK, 256>>>(x2, lin_w, lin_b, ga, gc);

    float* out = (float*)d_out;
    pair_kernel<<<N_TOK, N_TOK>>>(ga, gc, gt, out, rcel, rlnk);
    col_kernel<<<N_TOK, 128>>>(out, clnk);
    final_kernel<<<1, 512>>>(rcel, rlnk, clnk, out, out_size);
}